// round 1
// baseline (speedup 1.0000x reference)
#include <cuda_runtime.h>

typedef unsigned long long u64;

// Packed dual-fp32 FMA (Blackwell FFMA2) — only reachable via PTX f32x2.
#define FMA2(acc, a, b) asm("fma.rn.f32x2 %0, %1, %2, %0;" : "+l"(acc) : "l"(a), "l"(b))

__device__ __forceinline__ float hsum2(u64 v) {
    float lo, hi;
    asm("mov.b64 {%0, %1}, %2;" : "=f"(lo), "=f"(hi) : "l"(v));
    return lo + hi;
}

// Shapes (fixed by problem)
// B=64, C=256, H=W=56, WS=7, n1=n2=8, HEADS=16, DH=16, tokens/window=49
constexpr int TOK_STRIDE = 260;  // 49 x 260 fp32, k-fastest (16B aligned rows, conflict-free)
constexpr int W_STRIDE   = 132;  // 48 x 132 fp32, k-fastest
constexpr int QKV_STRIDE = 50;   // 49 x 50

struct SmemT {
    float tok[49][TOK_STRIDE];   // BN-normalized window tokens [t][c]
    float wst[48][W_STRIDE];     // staged per-head weights [oc][kk] (q:0-15,k:16-31,v:32-47)
    float qkv[49][QKV_STRIDE];   // per-head q|k|v
    float S[49][49];             // attention logits / probs
};

__global__ __launch_bounds__(256, 2)
void wsa_kernel(const float* __restrict__ x,
                const float* __restrict__ bng, const float* __restrict__ bnb,
                const float* __restrict__ bnm, const float* __restrict__ bnv,
                const float* __restrict__ qkw, const float* __restrict__ vw,
                float* __restrict__ out) {
    extern __shared__ char smem_raw[];
    SmemT& sm = *reinterpret_cast<SmemT*>(smem_raw);

    const int tid = threadIdx.x;
    const int wb  = blockIdx.x;        // window index = ((b*8)+n1)*8+n2
    const int b   = wb >> 6;
    const int n1  = (wb >> 3) & 7;
    const int n2  = wb & 7;

    // BatchNorm constants for channel c = tid (C == blockDim == 256)
    const float inv = bng[tid] / sqrtf(bnv[tid] + 1e-6f);
    const float shf = bnb[tid] - bnm[tid] * inv;

    // Load window tokens: pixel (h,w) = (ti*8+n1, tj*8+n2), token t = ti*7+tj
    const float* xb = x + ((size_t)b * 256 + tid) * 3136 + n1 * 56 + n2;
    #pragma unroll
    for (int t = 0; t < 49; ++t) {
        const int ti = t / 7, tj = t - (t / 7) * 7;
        sm.tok[t][tid] = fmaf(xb[ti * 448 + tj * 8], inv, shf);
    }

    const int ocg = tid & 15;          // 16 groups x 3 output channels (48 = q16|k16|v16)
    const int tg  = tid >> 4;          // 16 groups x 3 tokens (covers t 0..47)
    const int oc0 = ocg * 3;
    const int t0  = tg * 3;
    float* outb = out + (size_t)b * 256 * 3136 + n1 * 56 + n2;

    for (int head = 0; head < 16; ++head) {
        u64 acc[3][3];
        #pragma unroll
        for (int c = 0; c < 3; ++c)
            #pragma unroll
            for (int s = 0; s < 3; ++s) acc[c][s] = 0ull;
        u64 acc48a = 0ull, acc48b = 0ull;   // token-48 side accumulators (threads 0..47)

        for (int kt = 0; kt < 256; kt += 128) {
            __syncthreads();
            // Stage per-head weight slice, transposed to [oc][kk], vectorized.
            for (int idx = tid; idx < 48 * 32; idx += 256) {
                const int oc = idx >> 5;
                const int k4 = (idx & 31) << 2;
                const float* src;
                if (oc < 16)      src = qkw + (head * 16 + oc) * 256;              // q rows
                else if (oc < 32) src = qkw + (256 + head * 16 + (oc - 16)) * 256; // k rows
                else              src = vw  + (head * 16 + (oc - 32)) * 256;       // v rows
                *reinterpret_cast<float4*>(&sm.wst[oc][k4]) =
                    *reinterpret_cast<const float4*>(&src[kt + k4]);
            }
            __syncthreads();

            // Main projection: 3 oc x 3 t register tile, packed f32x2 over k.
            #pragma unroll 4
            for (int kk = 0; kk < 128; kk += 4) {
                const ulonglong2 xA = *reinterpret_cast<const ulonglong2*>(&sm.tok[t0 + 0][kt + kk]);
                const ulonglong2 xB = *reinterpret_cast<const ulonglong2*>(&sm.tok[t0 + 1][kt + kk]);
                const ulonglong2 xC = *reinterpret_cast<const ulonglong2*>(&sm.tok[t0 + 2][kt + kk]);
                const ulonglong2 w0 = *reinterpret_cast<const ulonglong2*>(&sm.wst[oc0 + 0][kk]);
                const ulonglong2 w1 = *reinterpret_cast<const ulonglong2*>(&sm.wst[oc0 + 1][kk]);
                const ulonglong2 w2 = *reinterpret_cast<const ulonglong2*>(&sm.wst[oc0 + 2][kk]);
                FMA2(acc[0][0], w0.x, xA.x); FMA2(acc[0][0], w0.y, xA.y);
                FMA2(acc[0][1], w0.x, xB.x); FMA2(acc[0][1], w0.y, xB.y);
                FMA2(acc[0][2], w0.x, xC.x); FMA2(acc[0][2], w0.y, xC.y);
                FMA2(acc[1][0], w1.x, xA.x); FMA2(acc[1][0], w1.y, xA.y);
                FMA2(acc[1][1], w1.x, xB.x); FMA2(acc[1][1], w1.y, xB.y);
                FMA2(acc[1][2], w1.x, xC.x); FMA2(acc[1][2], w1.y, xC.y);
                FMA2(acc[2][0], w2.x, xA.x); FMA2(acc[2][0], w2.y, xA.y);
                FMA2(acc[2][1], w2.x, xB.x); FMA2(acc[2][1], w2.y, xB.y);
                FMA2(acc[2][2], w2.x, xC.x); FMA2(acc[2][2], w2.y, xC.y);
            }

            // Token 48 (49 = 16*3 + 1): threads 0..47 each own one oc.
            if (tid < 48) {
                #pragma unroll 8
                for (int kk = 0; kk < 128; kk += 4) {
                    const ulonglong2 xx = *reinterpret_cast<const ulonglong2*>(&sm.tok[48][kt + kk]);
                    const ulonglong2 ww = *reinterpret_cast<const ulonglong2*>(&sm.wst[tid][kk]);
                    FMA2(acc48a, ww.x, xx.x);
                    FMA2(acc48b, ww.y, xx.y);
                }
            }
        }

        // Reduce packed accumulators, apply ReLU to v (oc >= 32), publish q|k|v.
        #pragma unroll
        for (int c = 0; c < 3; ++c)
            #pragma unroll
            for (int s = 0; s < 3; ++s) {
                float v = hsum2(acc[c][s]);
                const int oc = oc0 + c;
                if (oc >= 32) v = fmaxf(v, 0.f);
                sm.qkv[t0 + s][oc] = v;
            }
        if (tid < 48) {
            float v = hsum2(acc48a) + hsum2(acc48b);
            if (tid >= 32) v = fmaxf(v, 0.f);
            sm.qkv[48][tid] = v;
        }
        __syncthreads();

        // S = (q @ k^T) * dh^-0.5
        for (int idx = tid; idx < 49 * 49; idx += 256) {
            const int i = idx / 49, j = idx - i * 49;
            float s = 0.f;
            #pragma unroll
            for (int d = 0; d < 16; ++d)
                s = fmaf(sm.qkv[i][d], sm.qkv[j][16 + d], s);
            sm.S[i][j] = s * 0.25f;
        }
        __syncthreads();

        // Row softmax: warp w owns rows w, w+8, ...; 32 lanes cover 49 cols (2 per lane).
        {
            const int warp = tid >> 5, lane = tid & 31;
            for (int r = warp; r < 49; r += 8) {
                const float a = sm.S[r][lane];                       // lane < 32 < 49, always valid
                const bool hb = (lane + 32) < 49;
                const float bb = hb ? sm.S[r][lane + 32] : -1e30f;
                float m = fmaxf(a, bb);
                #pragma unroll
                for (int o = 16; o; o >>= 1) m = fmaxf(m, __shfl_xor_sync(0xffffffffu, m, o));
                const float e1 = __expf(a - m);
                const float e2 = hb ? __expf(bb - m) : 0.f;
                float sum = e1 + e2;
                #pragma unroll
                for (int o = 16; o; o >>= 1) sum += __shfl_xor_sync(0xffffffffu, sum, o);
                const float rs = 1.f / sum;
                sm.S[r][lane] = e1 * rs;
                if (hb) sm.S[r][lane + 32] = e2 * rs;
            }
        }
        __syncthreads();

        // O = P @ V, scatter straight to output layout (B, C, H, W)
        for (int idx = tid; idx < 49 * 16; idx += 256) {
            const int t = idx >> 4, d = idx & 15;
            float o = 0.f;
            #pragma unroll 7
            for (int j = 0; j < 49; ++j)
                o = fmaf(sm.S[t][j], sm.qkv[j][32 + d], o);
            const int ti = t / 7, tj = t - (t / 7) * 7;
            outb[(size_t)(head * 16 + d) * 3136 + ti * 448 + tj * 8] = o;
        }
        // next head's first __syncthreads() (weight staging) orders reuse of sm.qkv / sm.S
    }
}

extern "C" void kernel_launch(void* const* d_in, const int* in_sizes, int n_in,
                              void* d_out, int out_size) {
    const float* x   = (const float*)d_in[0];
    const float* g   = (const float*)d_in[1];
    const float* be  = (const float*)d_in[2];
    const float* mu  = (const float*)d_in[3];
    const float* var = (const float*)d_in[4];
    const float* qkw = (const float*)d_in[5];
    const float* vw  = (const float*)d_in[6];
    float* out = (float*)d_out;

    cudaFuncSetAttribute(wsa_kernel, cudaFuncAttributeMaxDynamicSharedMemorySize,
                         (int)sizeof(SmemT));
    wsa_kernel<<<4096, 256, sizeof(SmemT)>>>(x, g, be, mu, var, qkw, vw, out);
}

// round 2
// speedup vs baseline: 1.0016x; 1.0016x over previous
#include <cuda_runtime.h>

typedef unsigned long long u64;

// Packed dual-fp32 FMA (Blackwell FFMA2) — only reachable via PTX f32x2.
#define FMA2(acc, a, b) asm("fma.rn.f32x2 %0, %1, %2, %0;" : "+l"(acc) : "l"(a), "l"(b))

__device__ __forceinline__ float hsum2(u64 v) {
    float lo, hi;
    asm("mov.b64 {%0, %1}, %2;" : "=f"(lo), "=f"(hi) : "l"(v));
    return lo + hi;
}

// Shapes (fixed by problem)
// B=64, C=256, H=W=56, WS=7, n1=n2=8, HEADS=16, DH=16, tokens/window=49
constexpr int TOK_STRIDE = 260;  // 49 x 260 fp32, k-fastest (16B aligned rows, conflict-free)
constexpr int W_STRIDE   = 132;  // 48 x 132 fp32, k-fastest
constexpr int QKV_STRIDE = 50;   // 49 x 50

struct SmemT {
    float tok[49][TOK_STRIDE];   // BN-normalized window tokens [t][c]
    float wst[48][W_STRIDE];     // staged per-head weights [oc][kk] (q:0-15,k:16-31,v:32-47)
    float qkv[49][QKV_STRIDE];   // per-head q|k|v
    float S[49][49];             // attention logits / probs
};

__global__ __launch_bounds__(256, 2)
void wsa_kernel(const float* __restrict__ x,
                const float* __restrict__ bng, const float* __restrict__ bnb,
                const float* __restrict__ bnm, const float* __restrict__ bnv,
                const float* __restrict__ qkw, const float* __restrict__ vw,
                float* __restrict__ out) {
    extern __shared__ char smem_raw[];
    SmemT& sm = *reinterpret_cast<SmemT*>(smem_raw);

    const int tid = threadIdx.x;
    const int wb  = blockIdx.x;        // window index = ((b*8)+n1)*8+n2
    const int b   = wb >> 6;
    const int n1  = (wb >> 3) & 7;
    const int n2  = wb & 7;

    // BatchNorm constants for channel c = tid (C == blockDim == 256)
    const float inv = bng[tid] / sqrtf(bnv[tid] + 1e-6f);
    const float shf = bnb[tid] - bnm[tid] * inv;

    // Load window tokens: pixel (h,w) = (ti*8+n1, tj*8+n2), token t = ti*7+tj
    const float* xb = x + ((size_t)b * 256 + tid) * 3136 + n1 * 56 + n2;
    #pragma unroll
    for (int t = 0; t < 49; ++t) {
        const int ti = t / 7, tj = t - (t / 7) * 7;
        sm.tok[t][tid] = fmaf(xb[ti * 448 + tj * 8], inv, shf);
    }

    const int ocg = tid & 15;          // 16 groups x 3 output channels (48 = q16|k16|v16)
    const int tg  = tid >> 4;          // 16 groups x 3 tokens (covers t 0..47)
    const int oc0 = ocg * 3;
    const int t0  = tg * 3;
    float* outb = out + (size_t)b * 256 * 3136 + n1 * 56 + n2;

    for (int head = 0; head < 16; ++head) {
        u64 acc[3][3];
        #pragma unroll
        for (int c = 0; c < 3; ++c)
            #pragma unroll
            for (int s = 0; s < 3; ++s) acc[c][s] = 0ull;
        u64 acc48a = 0ull, acc48b = 0ull;   // token-48 side accumulators (threads 0..47)

        for (int kt = 0; kt < 256; kt += 128) {
            __syncthreads();
            // Stage per-head weight slice, transposed to [oc][kk], vectorized.
            for (int idx = tid; idx < 48 * 32; idx += 256) {
                const int oc = idx >> 5;
                const int k4 = (idx & 31) << 2;
                const float* src;
                if (oc < 16)      src = qkw + (head * 16 + oc) * 256;              // q rows
                else if (oc < 32) src = qkw + (256 + head * 16 + (oc - 16)) * 256; // k rows
                else              src = vw  + (head * 16 + (oc - 32)) * 256;       // v rows
                *reinterpret_cast<float4*>(&sm.wst[oc][k4]) =
                    *reinterpret_cast<const float4*>(&src[kt + k4]);
            }
            __syncthreads();

            // Main projection: 3 oc x 3 t register tile, packed f32x2 over k.
            #pragma unroll 4
            for (int kk = 0; kk < 128; kk += 4) {
                const ulonglong2 xA = *reinterpret_cast<const ulonglong2*>(&sm.tok[t0 + 0][kt + kk]);
                const ulonglong2 xB = *reinterpret_cast<const ulonglong2*>(&sm.tok[t0 + 1][kt + kk]);
                const ulonglong2 xC = *reinterpret_cast<const ulonglong2*>(&sm.tok[t0 + 2][kt + kk]);
                const ulonglong2 w0 = *reinterpret_cast<const ulonglong2*>(&sm.wst[oc0 + 0][kk]);
                const ulonglong2 w1 = *reinterpret_cast<const ulonglong2*>(&sm.wst[oc0 + 1][kk]);
                const ulonglong2 w2 = *reinterpret_cast<const ulonglong2*>(&sm.wst[oc0 + 2][kk]);
                FMA2(acc[0][0], w0.x, xA.x); FMA2(acc[0][0], w0.y, xA.y);
                FMA2(acc[0][1], w0.x, xB.x); FMA2(acc[0][1], w0.y, xB.y);
                FMA2(acc[0][2], w0.x, xC.x); FMA2(acc[0][2], w0.y, xC.y);
                FMA2(acc[1][0], w1.x, xA.x); FMA2(acc[1][0], w1.y, xA.y);
                FMA2(acc[1][1], w1.x, xB.x); FMA2(acc[1][1], w1.y, xB.y);
                FMA2(acc[1][2], w1.x, xC.x); FMA2(acc[1][2], w1.y, xC.y);
                FMA2(acc[2][0], w2.x, xA.x); FMA2(acc[2][0], w2.y, xA.y);
                FMA2(acc[2][1], w2.x, xB.x); FMA2(acc[2][1], w2.y, xB.y);
                FMA2(acc[2][2], w2.x, xC.x); FMA2(acc[2][2], w2.y, xC.y);
            }

            // Token 48 (49 = 16*3 + 1): threads 0..47 each own one oc.
            if (tid < 48) {
                #pragma unroll 8
                for (int kk = 0; kk < 128; kk += 4) {
                    const ulonglong2 xx = *reinterpret_cast<const ulonglong2*>(&sm.tok[48][kt + kk]);
                    const ulonglong2 ww = *reinterpret_cast<const ulonglong2*>(&sm.wst[tid][kk]);
                    FMA2(acc48a, ww.x, xx.x);
                    FMA2(acc48b, ww.y, xx.y);
                }
            }
        }

        // Reduce packed accumulators, apply ReLU to v (oc >= 32), publish q|k|v.
        #pragma unroll
        for (int c = 0; c < 3; ++c)
            #pragma unroll
            for (int s = 0; s < 3; ++s) {
                float v = hsum2(acc[c][s]);
                const int oc = oc0 + c;
                if (oc >= 32) v = fmaxf(v, 0.f);
                sm.qkv[t0 + s][oc] = v;
            }
        if (tid < 48) {
            float v = hsum2(acc48a) + hsum2(acc48b);
            if (tid >= 32) v = fmaxf(v, 0.f);
            sm.qkv[48][tid] = v;
        }
        __syncthreads();

        // S = (q @ k^T) * dh^-0.5
        for (int idx = tid; idx < 49 * 49; idx += 256) {
            const int i = idx / 49, j = idx - i * 49;
            float s = 0.f;
            #pragma unroll
            for (int d = 0; d < 16; ++d)
                s = fmaf(sm.qkv[i][d], sm.qkv[j][16 + d], s);
            sm.S[i][j] = s * 0.25f;
        }
        __syncthreads();

        // Row softmax: warp w owns rows w, w+8, ...; 32 lanes cover 49 cols (2 per lane).
        {
            const int warp = tid >> 5, lane = tid & 31;
            for (int r = warp; r < 49; r += 8) {
                const float a = sm.S[r][lane];                       // lane < 32 < 49, always valid
                const bool hb = (lane + 32) < 49;
                const float bb = hb ? sm.S[r][lane + 32] : -1e30f;
                float m = fmaxf(a, bb);
                #pragma unroll
                for (int o = 16; o; o >>= 1) m = fmaxf(m, __shfl_xor_sync(0xffffffffu, m, o));
                const float e1 = __expf(a - m);
                const float e2 = hb ? __expf(bb - m) : 0.f;
                float sum = e1 + e2;
                #pragma unroll
                for (int o = 16; o; o >>= 1) sum += __shfl_xor_sync(0xffffffffu, sum, o);
                const float rs = 1.f / sum;
                sm.S[r][lane] = e1 * rs;
                if (hb) sm.S[r][lane + 32] = e2 * rs;
            }
        }
        __syncthreads();

        // O = P @ V, scatter straight to output layout (B, C, H, W)
        for (int idx = tid; idx < 49 * 16; idx += 256) {
            const int t = idx >> 4, d = idx & 15;
            float o = 0.f;
            #pragma unroll 7
            for (int j = 0; j < 49; ++j)
                o = fmaf(sm.S[t][j], sm.qkv[j][32 + d], o);
            const int ti = t / 7, tj = t - (t / 7) * 7;
            outb[(size_t)(head * 16 + d) * 3136 + ti * 448 + tj * 8] = o;
        }
        // next head's first __syncthreads() (weight staging) orders reuse of sm.qkv / sm.S
    }
}

extern "C" void kernel_launch(void* const* d_in, const int* in_sizes, int n_in,
                              void* d_out, int out_size) {
    const float* x   = (const float*)d_in[0];
    const float* g   = (const float*)d_in[1];
    const float* be  = (const float*)d_in[2];
    const float* mu  = (const float*)d_in[3];
    const float* var = (const float*)d_in[4];
    const float* qkw = (const float*)d_in[5];
    const float* vw  = (const float*)d_in[6];
    float* out = (float*)d_out;

    cudaFuncSetAttribute(wsa_kernel, cudaFuncAttributeMaxDynamicSharedMemorySize,
                         (int)sizeof(SmemT));
    wsa_kernel<<<4096, 256, sizeof(SmemT)>>>(x, g, be, mu, var, qkw, vw, out);
}

// round 3
// speedup vs baseline: 1.0023x; 1.0006x over previous
#include <cuda_runtime.h>

typedef unsigned long long u64;

// Packed dual-fp32 FMA (Blackwell FFMA2) — only reachable via PTX f32x2.
#define FMA2(acc, a, b) asm("fma.rn.f32x2 %0, %1, %2, %0;" : "+l"(acc) : "l"(a), "l"(b))

__device__ __forceinline__ float hsum2(u64 v) {
    float lo, hi;
    asm("mov.b64 {%0, %1}, %2;" : "=f"(lo), "=f"(hi) : "l"(v));
    return lo + hi;
}

// Shapes (fixed by problem)
// B=64, C=256, H=W=56, WS=7, n1=n2=8, HEADS=16, DH=16, tokens/window=49
constexpr int TOK_STRIDE = 260;  // 49 x 260 fp32, k-fastest (16B aligned rows, conflict-free)
constexpr int W_STRIDE   = 132;  // 48 x 132 fp32, k-fastest
constexpr int QKV_STRIDE = 50;   // 49 x 50

struct SmemT {
    float tok[49][TOK_STRIDE];   // BN-normalized window tokens [t][c]
    float wst[48][W_STRIDE];     // staged per-head weights [oc][kk] (q:0-15,k:16-31,v:32-47)
    float qkv[49][QKV_STRIDE];   // per-head q|k|v
    float S[49][49];             // attention logits / probs
};

__global__ __launch_bounds__(256, 2)
void wsa_kernel(const float* __restrict__ x,
                const float* __restrict__ bng, const float* __restrict__ bnb,
                const float* __restrict__ bnm, const float* __restrict__ bnv,
                const float* __restrict__ qkw, const float* __restrict__ vw,
                float* __restrict__ out) {
    extern __shared__ char smem_raw[];
    SmemT& sm = *reinterpret_cast<SmemT*>(smem_raw);

    const int tid = threadIdx.x;
    const int wb  = blockIdx.x;        // window index = ((b*8)+n1)*8+n2
    const int b   = wb >> 6;
    const int n1  = (wb >> 3) & 7;
    const int n2  = wb & 7;

    // BatchNorm constants for channel c = tid (C == blockDim == 256)
    const float inv = bng[tid] / sqrtf(bnv[tid] + 1e-6f);
    const float shf = bnb[tid] - bnm[tid] * inv;

    // Load window tokens: pixel (h,w) = (ti*8+n1, tj*8+n2), token t = ti*7+tj
    const float* xb = x + ((size_t)b * 256 + tid) * 3136 + n1 * 56 + n2;
    #pragma unroll
    for (int t = 0; t < 49; ++t) {
        const int ti = t / 7, tj = t - (t / 7) * 7;
        sm.tok[t][tid] = fmaf(xb[ti * 448 + tj * 8], inv, shf);
    }

    const int ocg = tid & 15;          // 16 groups x 3 output channels (48 = q16|k16|v16)
    const int tg  = tid >> 4;          // 16 groups x 3 tokens (covers t 0..47)
    const int oc0 = ocg * 3;
    const int t0  = tg * 3;
    float* outb = out + (size_t)b * 256 * 3136 + n1 * 56 + n2;

    for (int head = 0; head < 16; ++head) {
        u64 acc[3][3];
        #pragma unroll
        for (int c = 0; c < 3; ++c)
            #pragma unroll
            for (int s = 0; s < 3; ++s) acc[c][s] = 0ull;
        u64 acc48a = 0ull, acc48b = 0ull;   // token-48 side accumulators (threads 0..47)

        for (int kt = 0; kt < 256; kt += 128) {
            __syncthreads();
            // Stage per-head weight slice, transposed to [oc][kk], vectorized.
            for (int idx = tid; idx < 48 * 32; idx += 256) {
                const int oc = idx >> 5;
                const int k4 = (idx & 31) << 2;
                const float* src;
                if (oc < 16)      src = qkw + (head * 16 + oc) * 256;              // q rows
                else if (oc < 32) src = qkw + (256 + head * 16 + (oc - 16)) * 256; // k rows
                else              src = vw  + (head * 16 + (oc - 32)) * 256;       // v rows
                *reinterpret_cast<float4*>(&sm.wst[oc][k4]) =
                    *reinterpret_cast<const float4*>(&src[kt + k4]);
            }
            __syncthreads();

            // Main projection: 3 oc x 3 t register tile, packed f32x2 over k.
            #pragma unroll 4
            for (int kk = 0; kk < 128; kk += 4) {
                const ulonglong2 xA = *reinterpret_cast<const ulonglong2*>(&sm.tok[t0 + 0][kt + kk]);
                const ulonglong2 xB = *reinterpret_cast<const ulonglong2*>(&sm.tok[t0 + 1][kt + kk]);
                const ulonglong2 xC = *reinterpret_cast<const ulonglong2*>(&sm.tok[t0 + 2][kt + kk]);
                const ulonglong2 w0 = *reinterpret_cast<const ulonglong2*>(&sm.wst[oc0 + 0][kk]);
                const ulonglong2 w1 = *reinterpret_cast<const ulonglong2*>(&sm.wst[oc0 + 1][kk]);
                const ulonglong2 w2 = *reinterpret_cast<const ulonglong2*>(&sm.wst[oc0 + 2][kk]);
                FMA2(acc[0][0], w0.x, xA.x); FMA2(acc[0][0], w0.y, xA.y);
                FMA2(acc[0][1], w0.x, xB.x); FMA2(acc[0][1], w0.y, xB.y);
                FMA2(acc[0][2], w0.x, xC.x); FMA2(acc[0][2], w0.y, xC.y);
                FMA2(acc[1][0], w1.x, xA.x); FMA2(acc[1][0], w1.y, xA.y);
                FMA2(acc[1][1], w1.x, xB.x); FMA2(acc[1][1], w1.y, xB.y);
                FMA2(acc[1][2], w1.x, xC.x); FMA2(acc[1][2], w1.y, xC.y);
                FMA2(acc[2][0], w2.x, xA.x); FMA2(acc[2][0], w2.y, xA.y);
                FMA2(acc[2][1], w2.x, xB.x); FMA2(acc[2][1], w2.y, xB.y);
                FMA2(acc[2][2], w2.x, xC.x); FMA2(acc[2][2], w2.y, xC.y);
            }

            // Token 48 (49 = 16*3 + 1): threads 0..47 each own one oc.
            if (tid < 48) {
                #pragma unroll 8
                for (int kk = 0; kk < 128; kk += 4) {
                    const ulonglong2 xx = *reinterpret_cast<const ulonglong2*>(&sm.tok[48][kt + kk]);
                    const ulonglong2 ww = *reinterpret_cast<const ulonglong2*>(&sm.wst[tid][kk]);
                    FMA2(acc48a, ww.x, xx.x);
                    FMA2(acc48b, ww.y, xx.y);
                }
            }
        }

        // Reduce packed accumulators, apply ReLU to v (oc >= 32), publish q|k|v.
        #pragma unroll
        for (int c = 0; c < 3; ++c)
            #pragma unroll
            for (int s = 0; s < 3; ++s) {
                float v = hsum2(acc[c][s]);
                const int oc = oc0 + c;
                if (oc >= 32) v = fmaxf(v, 0.f);
                sm.qkv[t0 + s][oc] = v;
            }
        if (tid < 48) {
            float v = hsum2(acc48a) + hsum2(acc48b);
            if (tid >= 32) v = fmaxf(v, 0.f);
            sm.qkv[48][tid] = v;
        }
        __syncthreads();

        // S = (q @ k^T) * dh^-0.5
        for (int idx = tid; idx < 49 * 49; idx += 256) {
            const int i = idx / 49, j = idx - i * 49;
            float s = 0.f;
            #pragma unroll
            for (int d = 0; d < 16; ++d)
                s = fmaf(sm.qkv[i][d], sm.qkv[j][16 + d], s);
            sm.S[i][j] = s * 0.25f;
        }
        __syncthreads();

        // Row softmax: warp w owns rows w, w+8, ...; 32 lanes cover 49 cols (2 per lane).
        {
            const int warp = tid >> 5, lane = tid & 31;
            for (int r = warp; r < 49; r += 8) {
                const float a = sm.S[r][lane];                       // lane < 32 < 49, always valid
                const bool hb = (lane + 32) < 49;
                const float bb = hb ? sm.S[r][lane + 32] : -1e30f;
                float m = fmaxf(a, bb);
                #pragma unroll
                for (int o = 16; o; o >>= 1) m = fmaxf(m, __shfl_xor_sync(0xffffffffu, m, o));
                const float e1 = __expf(a - m);
                const float e2 = hb ? __expf(bb - m) : 0.f;
                float sum = e1 + e2;
                #pragma unroll
                for (int o = 16; o; o >>= 1) sum += __shfl_xor_sync(0xffffffffu, sum, o);
                const float rs = 1.f / sum;
                sm.S[r][lane] = e1 * rs;
                if (hb) sm.S[r][lane + 32] = e2 * rs;
            }
        }
        __syncthreads();

        // O = P @ V, scatter straight to output layout (B, C, H, W)
        for (int idx = tid; idx < 49 * 16; idx += 256) {
            const int t = idx >> 4, d = idx & 15;
            float o = 0.f;
            #pragma unroll 7
            for (int j = 0; j < 49; ++j)
                o = fmaf(sm.S[t][j], sm.qkv[j][32 + d], o);
            const int ti = t / 7, tj = t - (t / 7) * 7;
            outb[(size_t)(head * 16 + d) * 3136 + ti * 448 + tj * 8] = o;
        }
        // next head's first __syncthreads() (weight staging) orders reuse of sm.qkv / sm.S
    }
}

extern "C" void kernel_launch(void* const* d_in, const int* in_sizes, int n_in,
                              void* d_out, int out_size) {
    const float* x   = (const float*)d_in[0];
    const float* g   = (const float*)d_in[1];
    const float* be  = (const float*)d_in[2];
    const float* mu  = (const float*)d_in[3];
    const float* var = (const float*)d_in[4];
    const float* qkw = (const float*)d_in[5];
    const float* vw  = (const float*)d_in[6];
    float* out = (float*)d_out;

    cudaFuncSetAttribute(wsa_kernel, cudaFuncAttributeMaxDynamicSharedMemorySize,
                         (int)sizeof(SmemT));
    wsa_kernel<<<4096, 256, sizeof(SmemT)>>>(x, g, be, mu, var, qkw, vw, out);
}

// round 4
// speedup vs baseline: 1.0503x; 1.0479x over previous
#include <cuda_runtime.h>

typedef unsigned long long u64;

// Packed dual-fp32 FMA (Blackwell FFMA2) — only reachable via PTX f32x2.
#define FMA2(acc, a, b) asm("fma.rn.f32x2 %0, %1, %2, %0;" : "+l"(acc) : "l"(a), "l"(b))

__device__ __forceinline__ float hsum2(u64 v) {
    float lo, hi;
    asm("mov.b64 {%0, %1}, %2;" : "=f"(lo), "=f"(hi) : "l"(v));
    return lo + hi;
}

// Shapes: B=64, C=256, H=W=56, WS=7, n1=n2=8, HEADS=16, DH=16, 49 tokens/window
constexpr int TOK_STRIDE = 260;  // token rows: stride-3 row access -> bank offsets {0,12,24,4}: conflict-free
constexpr int W_STRIDE   = 68;   // 64-k chunk + pad: row step bank offset = 68%32 = 4 -> perfect 32-bank spread
constexpr int QKV_STRIDE = 50;
constexpr int S_STRIDE   = 52;

struct SmemT {
    float tok[49][TOK_STRIDE];    // BN'd window tokens [t][c]           (50960 B)
    float wst[96][W_STRIDE];      // staged weights [h2*48+oc][kk]       (26112 B)
    float qkv[2][49][QKV_STRIDE]; // 2 heads of q|k|v                    (19600 B)
    float S[49][S_STRIDE];        // one head's logits/probs             (10192 B)
};                                // total ~104.4 KB -> 2 CTAs/SM

__global__ __launch_bounds__(256, 2)
void wsa_kernel(const float* __restrict__ x,
                const float* __restrict__ bng, const float* __restrict__ bnb,
                const float* __restrict__ bnm, const float* __restrict__ bnv,
                const float* __restrict__ qkw, const float* __restrict__ vw,
                float* __restrict__ out) {
    extern __shared__ char smem_raw[];
    SmemT& sm = *reinterpret_cast<SmemT*>(smem_raw);

    const int tid = threadIdx.x;
    const int wb  = blockIdx.x;        // window index = ((b*8)+n1)*8+n2
    const int b   = wb >> 6;
    const int n1  = (wb >> 3) & 7;
    const int n2  = wb & 7;

    // BatchNorm constants for channel c = tid (C == blockDim == 256)
    const float inv = bng[tid] / sqrtf(bnv[tid] + 1e-6f);
    const float shf = bnb[tid] - bnm[tid] * inv;

    // Load window tokens: pixel (h,w) = (ti*8+n1, tj*8+n2), token t = ti*7+tj
    const float* xb = x + ((size_t)b * 256 + tid) * 3136 + n1 * 56 + n2;
    #pragma unroll 7
    for (int t = 0; t < 49; ++t) {
        const int ti = t / 7, tj = t - (t / 7) * 7;
        sm.tok[t][tid] = fmaf(xb[ti * 448 + tj * 8], inv, shf);
    }

    // Thread mapping: 2 heads x 8 oc-groups x 16 token-groups.
    // Each thread: 6 oc (interleaved: oc = ocg + 8c) x 3 tokens.
    const int ocg = tid & 7;
    const int tg  = (tid >> 3) & 15;
    const int h2  = tid >> 7;
    const int t0  = tg * 3;
    // Tail ownership (token 48): threads 0..95 -> wst row = tid directly.
    const int oc48 = (tid < 48) ? tid : tid - 48;

    float* outb = out + (size_t)b * 256 * 3136 + n1 * 56 + n2;

    for (int hp = 0; hp < 8; ++hp) {           // head pair: heads 2hp, 2hp+1
        u64 acc[6][3];
        #pragma unroll
        for (int c = 0; c < 6; ++c)
            #pragma unroll
            for (int s = 0; s < 3; ++s) acc[c][s] = 0ull;
        u64 acc48 = 0ull;

        for (int kt = 0; kt < 256; kt += 64) {
            __syncthreads();
            // Stage 96 weight rows (2 heads x 48 oc) x 64 k, vectorized.
            for (int idx = tid; idx < 96 * 16; idx += 256) {
                const int r  = idx >> 4;           // 0..95
                const int k4 = (idx & 15) << 2;
                const int hh = (r >= 48);
                const int oc = r - hh * 48;
                const int head = hp * 2 + hh;
                const float* src;
                if (oc < 16)      src = qkw + (head * 16 + oc) * 256;               // q rows
                else if (oc < 32) src = qkw + (256 + head * 16 + (oc - 16)) * 256;  // k rows
                else              src = vw  + (head * 16 + (oc - 32)) * 256;        // v rows
                *reinterpret_cast<float4*>(&sm.wst[r][k4]) =
                    *reinterpret_cast<const float4*>(&src[kt + k4]);
            }
            __syncthreads();

            const float* wbase = &sm.wst[h2 * 48 + ocg][0];
            const float* tA = &sm.tok[t0 + 0][kt];
            const float* tB = &sm.tok[t0 + 1][kt];
            const float* tC = &sm.tok[t0 + 2][kt];

            #pragma unroll 2
            for (int kk = 0; kk < 64; kk += 4) {
                const ulonglong2 xA = *reinterpret_cast<const ulonglong2*>(&tA[kk]);
                const ulonglong2 xB = *reinterpret_cast<const ulonglong2*>(&tB[kk]);
                const ulonglong2 xC = *reinterpret_cast<const ulonglong2*>(&tC[kk]);
                #pragma unroll
                for (int c = 0; c < 6; ++c) {
                    const ulonglong2 w =
                        *reinterpret_cast<const ulonglong2*>(&wbase[c * 8 * W_STRIDE + kk]);
                    FMA2(acc[c][0], w.x, xA.x); FMA2(acc[c][0], w.y, xA.y);
                    FMA2(acc[c][1], w.x, xB.x); FMA2(acc[c][1], w.y, xB.y);
                    FMA2(acc[c][2], w.x, xC.x); FMA2(acc[c][2], w.y, xC.y);
                }
            }

            // Token 48 tail: threads 0..95 each own one (h, oc) = wst row tid.
            if (tid < 96) {
                const float* wt = &sm.wst[tid][0];
                #pragma unroll 4
                for (int kk = 0; kk < 64; kk += 4) {
                    const ulonglong2 xx = *reinterpret_cast<const ulonglong2*>(&sm.tok[48][kt + kk]);
                    const ulonglong2 ww = *reinterpret_cast<const ulonglong2*>(&wt[kk]);
                    FMA2(acc48, ww.x, xx.x);
                    FMA2(acc48, ww.y, xx.y);
                }
            }
        }

        // Publish q|k|v (ReLU on v: c>=4 <=> oc>=32).
        #pragma unroll
        for (int c = 0; c < 6; ++c) {
            const int oc = ocg + 8 * c;
            #pragma unroll
            for (int s = 0; s < 3; ++s) {
                float v = hsum2(acc[c][s]);
                if (c >= 4) v = fmaxf(v, 0.f);
                sm.qkv[h2][t0 + s][oc] = v;
            }
        }
        if (tid < 96) {
            float v = hsum2(acc48);
            if (oc48 >= 32) v = fmaxf(v, 0.f);
            sm.qkv[tid < 48 ? 0 : 1][48][oc48] = v;
        }
        __syncthreads();

        // Attention for the two heads, sequentially (shared S buffer).
        for (int ah = 0; ah < 2; ++ah) {
            // S = (q @ k^T) * dh^-0.5
            for (int idx = tid; idx < 49 * 49; idx += 256) {
                const int i = idx / 49, j = idx - i * 49;
                float s = 0.f;
                #pragma unroll
                for (int d = 0; d < 16; ++d)
                    s = fmaf(sm.qkv[ah][i][d], sm.qkv[ah][j][16 + d], s);
                sm.S[i][j] = s * 0.25f;
            }
            __syncthreads();

            // Row softmax: warp w owns rows w, w+8, ...
            {
                const int warp = tid >> 5, lane = tid & 31;
                for (int r = warp; r < 49; r += 8) {
                    const float a = sm.S[r][lane];
                    const bool hb = (lane + 32) < 49;
                    const float bb = hb ? sm.S[r][lane + 32] : -1e30f;
                    float m = fmaxf(a, bb);
                    #pragma unroll
                    for (int o = 16; o; o >>= 1) m = fmaxf(m, __shfl_xor_sync(0xffffffffu, m, o));
                    const float e1 = __expf(a - m);
                    const float e2 = hb ? __expf(bb - m) : 0.f;
                    float sum = e1 + e2;
                    #pragma unroll
                    for (int o = 16; o; o >>= 1) sum += __shfl_xor_sync(0xffffffffu, sum, o);
                    const float rs = 1.f / sum;
                    sm.S[r][lane] = e1 * rs;
                    if (hb) sm.S[r][lane + 32] = e2 * rs;
                }
            }
            __syncthreads();

            // O = P @ V, scatter straight to (B, C, H, W)
            const int head = hp * 2 + ah;
            for (int idx = tid; idx < 49 * 16; idx += 256) {
                const int t = idx >> 4, d = idx & 15;
                float o = 0.f;
                #pragma unroll 7
                for (int j = 0; j < 49; ++j)
                    o = fmaf(sm.S[t][j], sm.qkv[ah][j][32 + d], o);
                const int ti = t / 7, tj = t - (t / 7) * 7;
                outb[(size_t)(head * 16 + d) * 3136 + ti * 448 + tj * 8] = o;
            }
            __syncthreads();  // S / qkv reuse ordering
        }
    }
}

extern "C" void kernel_launch(void* const* d_in, const int* in_sizes, int n_in,
                              void* d_out, int out_size) {
    const float* x   = (const float*)d_in[0];
    const float* g   = (const float*)d_in[1];
    const float* be  = (const float*)d_in[2];
    const float* mu  = (const float*)d_in[3];
    const float* var = (const float*)d_in[4];
    const float* qkw = (const float*)d_in[5];
    const float* vw  = (const float*)d_in[6];
    float* out = (float*)d_out;

    cudaFuncSetAttribute(wsa_kernel, cudaFuncAttributeMaxDynamicSharedMemorySize,
                         (int)sizeof(SmemT));
    wsa_kernel<<<4096, 256, sizeof(SmemT)>>>(x, g, be, mu, var, qkw, vw, out);
}

// round 5
// speedup vs baseline: 1.3259x; 1.2625x over previous
#include <cuda_runtime.h>

typedef unsigned long long u64;

// Packed dual-fp32 FMA (Blackwell FFMA2) — only reachable via PTX f32x2.
#define FMA2(acc, a, b) asm("fma.rn.f32x2 %0, %1, %2, %0;" : "+l"(acc) : "l"(a), "l"(b))

__device__ __forceinline__ float hsum2(u64 v) {
    float lo, hi;
    asm("mov.b64 {%0, %1}, %2;" : "=f"(lo), "=f"(hi) : "l"(v));
    return lo + hi;
}

// Shapes: B=64, C=256, H=W=56, WS=7, n1=n2=8, HEADS=16, DH=16, 49 tokens/window
constexpr int TOK_STRIDE = 256;  // tok reads are warp-uniform broadcast; writes lane-consecutive
constexpr int W_STRIDE   = 36;   // lane offsets 36*l: 4l mod 32 tiles all banks -> minimal 4 wf / LDS.128
constexpr int QT_STRIDE  = 57;   // odd stride: publish STS (lane-stride 57) conflict-free
constexpr int ST_STRIDE  = 50;   // st reads/writes lane-consecutive in i

struct SmemT {
    float tok[56][TOK_STRIDE];   // BN'd tokens [t][c], rows 49..55 zero      (57344 B)
    float wst[96][W_STRIDE];     // head-pair weights [hh*48+oc][k32]         (13824 B)
    float qt[96][QT_STRIDE];     // q|k|v transposed [hh*48+oc][t]            (21888 B)
    float st[2][49][ST_STRIDE];  // logits/probs transposed [hh][j][i]        (19600 B)
};                               // total 112656 B -> 2 CTAs/SM

__global__ __launch_bounds__(256, 2)
void wsa_kernel(const float* __restrict__ x,
                const float* __restrict__ bng, const float* __restrict__ bnb,
                const float* __restrict__ bnm, const float* __restrict__ bnv,
                const float* __restrict__ qkw, const float* __restrict__ vw,
                float* __restrict__ out) {
    extern __shared__ char smem_raw[];
    SmemT& sm = *reinterpret_cast<SmemT*>(smem_raw);

    const int tid  = threadIdx.x;
    const int lane = tid & 31;
    const int warp = tid >> 5;
    const int wb   = blockIdx.x;       // window index = ((b*8)+n1)*8+n2
    const int b    = wb >> 6;
    const int n1   = (wb >> 3) & 7;
    const int n2   = wb & 7;

    // BatchNorm constants for channel c = tid (C == blockDim == 256)
    const float inv = bng[tid] / sqrtf(bnv[tid] + 1e-6f);
    const float shf = bnb[tid] - bnm[tid] * inv;

    // Load window tokens: pixel (h,w) = (ti*8+n1, tj*8+n2), token t = ti*7+tj
    const float* xb = x + ((size_t)b * 256 + tid) * 3136 + n1 * 56 + n2;
    #pragma unroll 7
    for (int t = 0; t < 49; ++t) {
        const int ti = t / 7, tj = t - (t / 7) * 7;
        sm.tok[t][tid] = fmaf(xb[ti * 448 + tj * 8], inv, shf);
    }
    #pragma unroll
    for (int t = 49; t < 56; ++t) sm.tok[t][tid] = 0.f;  // pad rows

    const int t0 = warp * 7;           // this warp's 7 tokens
    float* outb = out + (size_t)b * 256 * 3136 + n1 * 56 + n2;

    for (int hp = 0; hp < 8; ++hp) {   // head pair: heads 2hp, 2hp+1
        // ---------------- Projection GEMM: 56 tok x 96 oc x 256 k ----------------
        u64 acc[3][7];
        #pragma unroll
        for (int c = 0; c < 3; ++c)
            #pragma unroll
            for (int s = 0; s < 7; ++s) acc[c][s] = 0ull;

        for (int kt = 0; kt < 256; kt += 32) {
            __syncthreads();
            // Stage 96 weight rows x 32 k (3 float4 per thread).
            #pragma unroll
            for (int ii = 0; ii < 3; ++ii) {
                const int idx = tid + ii * 256;          // 0..767
                const int r  = idx >> 3;
                const int k4 = (idx & 7) << 2;
                const int hh = (r >= 48);
                const int oc = r - hh * 48;
                const int head = hp * 2 + hh;
                const float* src;
                if (oc < 16)      src = qkw + (head * 16 + oc) * 256;               // q
                else if (oc < 32) src = qkw + (256 + head * 16 + (oc - 16)) * 256;  // k
                else              src = vw  + (head * 16 + (oc - 32)) * 256;        // v
                *reinterpret_cast<float4*>(&sm.wst[r][k4]) =
                    *reinterpret_cast<const float4*>(&src[kt + k4]);
            }
            __syncthreads();

            #pragma unroll 4
            for (int kk = 0; kk < 32; kk += 4) {
                ulonglong2 xs[7];
                #pragma unroll
                for (int s = 0; s < 7; ++s)   // warp-uniform address -> broadcast, 1 wf
                    xs[s] = *reinterpret_cast<const ulonglong2*>(&sm.tok[t0 + s][kt + kk]);
                #pragma unroll
                for (int c = 0; c < 3; ++c) {
                    const ulonglong2 w =
                        *reinterpret_cast<const ulonglong2*>(&sm.wst[lane + 32 * c][kk]);
                    #pragma unroll
                    for (int s = 0; s < 7; ++s) {
                        FMA2(acc[c][s], w.x, xs[s].x);
                        FMA2(acc[c][s], w.y, xs[s].y);
                    }
                }
            }
        }

        // Publish q|k|v transposed. oc96 = lane + 32c; ReLU on v rows.
        #pragma unroll
        for (int c = 0; c < 3; ++c) {
            const int o = lane + 32 * c;
            const bool relu = (o < 48) ? (o >= 32) : (o >= 80);
            #pragma unroll
            for (int s = 0; s < 7; ++s) {
                float v = hsum2(acc[c][s]);
                if (relu) v = fmaxf(v, 0.f);
                sm.qt[o][t0 + s] = v;      // lane-stride 57 -> conflict-free
            }
        }
        __syncthreads();

        // ---------------- S = (q @ k^T) * 0.25, both heads in parallel ----------------
        {
            const int hh   = warp >> 2;
            const int wq   = warp & 3;
            const int base = hh * 48;
            const bool act1 = (lane + 32) < 49;
            float q0[16], q1[16];
            #pragma unroll
            for (int d = 0; d < 16; ++d) {
                q0[d] = sm.qt[base + d][lane];                    // lane-consecutive
                q1[d] = act1 ? sm.qt[base + d][lane + 32] : 0.f;
            }
            #pragma unroll 1
            for (int jj = 0; jj < 13; ++jj) {
                const int j = wq * 13 + jj;
                if (j < 49) {
                    float s0 = 0.f, s1 = 0.f;
                    #pragma unroll
                    for (int d = 0; d < 16; ++d) {
                        const float kv = sm.qt[base + 16 + d][j];  // warp-uniform broadcast
                        s0 = fmaf(kv, q0[d], s0);
                        s1 = fmaf(kv, q1[d], s1);
                    }
                    sm.st[hh][j][lane] = s0 * 0.25f;
                    if (act1) sm.st[hh][j][lane + 32] = s1 * 0.25f;
                }
            }
        }
        __syncthreads();

        // ---------------- softmax over j (per query i, fully independent) ----------------
        if (tid < 98) {
            const int hh = tid >= 49;
            const int i  = tid - hh * 49;
            float m = -1e30f;
            #pragma unroll 7
            for (int j = 0; j < 49; ++j) m = fmaxf(m, sm.st[hh][j][i]);
            float sum = 0.f;
            #pragma unroll 7
            for (int j = 0; j < 49; ++j) {
                const float e = __expf(sm.st[hh][j][i] - m);
                sm.st[hh][j][i] = e;
                sum += e;
            }
            const float rs = 1.f / sum;
            #pragma unroll 7
            for (int j = 0; j < 49; ++j) sm.st[hh][j][i] *= rs;
        }
        __syncthreads();

        // ---------------- O = P @ V, scatter to (B, C, H, W) ----------------
        {
            const int hh   = warp >> 2;
            const int base = hh * 48 + 32;
            const int head = hp * 2 + hh;
            const bool act1 = (lane + 32) < 49;
            #pragma unroll
            for (int dd = 0; dd < 4; ++dd) {
                const int d = (warp & 3) * 4 + dd;
                float o0 = 0.f, o1 = 0.f;
                #pragma unroll 7
                for (int j = 0; j < 49; ++j) {
                    const float vb = sm.qt[base + d][j];          // warp-uniform broadcast
                    o0 = fmaf(vb, sm.st[hh][j][lane], o0);        // lane-consecutive
                    o1 = fmaf(vb, act1 ? sm.st[hh][j][lane + 32] : 0.f, o1);
                }
                const size_t ch = (size_t)(head * 16 + d) * 3136;
                {
                    const int i = lane, ti = i / 7, tj = i - (i / 7) * 7;
                    outb[ch + ti * 448 + tj * 8] = o0;
                }
                if (act1) {
                    const int i = lane + 32, ti = i / 7, tj = i - (i / 7) * 7;
                    outb[ch + ti * 448 + tj * 8] = o1;
                }
            }
        }
        __syncthreads();   // st / qt reuse ordering for next head pair
    }
}

extern "C" void kernel_launch(void* const* d_in, const int* in_sizes, int n_in,
                              void* d_out, int out_size) {
    const float* x   = (const float*)d_in[0];
    const float* g   = (const float*)d_in[1];
    const float* be  = (const float*)d_in[2];
    const float* mu  = (const float*)d_in[3];
    const float* var = (const float*)d_in[4];
    const float* qkw = (const float*)d_in[5];
    const float* vw  = (const float*)d_in[6];
    float* out = (float*)d_out;

    cudaFuncSetAttribute(wsa_kernel, cudaFuncAttributeMaxDynamicSharedMemorySize,
                         (int)sizeof(SmemT));
    wsa_kernel<<<4096, 256, sizeof(SmemT)>>>(x, g, be, mu, var, qkw, vw, out);
}

// round 6
// speedup vs baseline: 1.3325x; 1.0050x over previous
#include <cuda_runtime.h>

typedef unsigned long long u64;

// Packed dual-fp32 FMA (Blackwell FFMA2) — only reachable via PTX f32x2.
#define FMA2(acc, a, b) asm("fma.rn.f32x2 %0, %1, %2, %0;" : "+l"(acc) : "l"(a), "l"(b))

__device__ __forceinline__ float hsum2(u64 v) {
    float lo, hi;
    asm("mov.b64 {%0, %1}, %2;" : "=f"(lo), "=f"(hi) : "l"(v));
    return lo + hi;
}

// Shapes: B=64, C=256, H=W=56, WS=7, n1=n2=8, HEADS=16, DH=16, 49 tokens/window
constexpr int TOK_STRIDE = 260;  // 7*260 mod 32 = 28 -> the two half-warp token addrs hit disjoint banks (1 wf)
constexpr int W_STRIDE   = 36;   // 16 rows x stride 36: 256B in exactly 2 wavefronts
constexpr int QT_STRIDE  = 57;   // publish STS conflict-free; covers t<57
constexpr int ST_STRIDE  = 50;

struct SmemT {
    float tok[56][TOK_STRIDE];   // BN'd tokens [t][c], rows 49..55 zero      (58240 B)
    float wst[96][W_STRIDE];     // head-pair weights [hh*48+oc][k32]         (13824 B)
    float qt[96][QT_STRIDE];     // q|k|v transposed [hh*48+oc][t]            (21888 B)
    float st[2][49][ST_STRIDE];  // logits/probs transposed [hh][j][i]        (19600 B)
};                               // total 113552 B -> 2 CTAs/SM

__global__ __launch_bounds__(256, 2)
void wsa_kernel(const float* __restrict__ x,
                const float* __restrict__ bng, const float* __restrict__ bnb,
                const float* __restrict__ bnm, const float* __restrict__ bnv,
                const float* __restrict__ qkw, const float* __restrict__ vw,
                float* __restrict__ out) {
    extern __shared__ char smem_raw[];
    SmemT& sm = *reinterpret_cast<SmemT*>(smem_raw);

    const int tid  = threadIdx.x;
    const int lane = tid & 31;
    const int warp = tid >> 5;
    const int wb   = blockIdx.x;       // window index = ((b*8)+n1)*8+n2
    const int b    = wb >> 6;
    const int n1   = (wb >> 3) & 7;
    const int n2   = wb & 7;

    // BatchNorm constants for channel c = tid (C == blockDim == 256)
    const float inv = bng[tid] / sqrtf(bnv[tid] + 1e-6f);
    const float shf = bnb[tid] - bnm[tid] * inv;

    // Load window tokens: pixel (h,w) = (ti*8+n1, tj*8+n2), token t = ti*7+tj
    const float* xb = x + ((size_t)b * 256 + tid) * 3136 + n1 * 56 + n2;
    #pragma unroll 7
    for (int t = 0; t < 49; ++t) {
        const int ti = t / 7, tj = t - (t / 7) * 7;
        sm.tok[t][tid] = fmaf(xb[ti * 448 + tj * 8], inv, shf);
    }
    #pragma unroll
    for (int t = 49; t < 56; ++t) sm.tok[t][tid] = 0.f;  // pad rows

    // Projection mapping: warp = 16 oc x 14 tokens (7 per half-warp).
    // Lane pairs (l, l+16) share the SAME weight rows -> weight LDS.128 = 2 wf.
    const int hh   = warp >> 2;        // head within pair
    const int wq   = warp & 3;         // token quarter
    const int oc16 = lane & 15;
    const int t0   = wq * 14 + (lane >> 4) * 7;   // this thread's 7 tokens

    float* outb = out + (size_t)b * 256 * 3136 + n1 * 56 + n2;

    for (int hp = 0; hp < 8; ++hp) {   // head pair: heads 2hp, 2hp+1
        // ---------------- Projection GEMM: 56 tok x 96 oc x 256 k ----------------
        u64 acc[3][7];
        #pragma unroll
        for (int c = 0; c < 3; ++c)
            #pragma unroll
            for (int s = 0; s < 7; ++s) acc[c][s] = 0ull;

        for (int kt = 0; kt < 256; kt += 32) {
            __syncthreads();
            // Stage 96 weight rows x 32 k (3 float4 per thread).
            #pragma unroll
            for (int ii = 0; ii < 3; ++ii) {
                const int idx = tid + ii * 256;          // 0..767
                const int r  = idx >> 3;
                const int k4 = (idx & 7) << 2;
                const int hw = (r >= 48);
                const int oc = r - hw * 48;
                const int head = hp * 2 + hw;
                const float* src;
                if (oc < 16)      src = qkw + (head * 16 + oc) * 256;               // q
                else if (oc < 32) src = qkw + (256 + head * 16 + (oc - 16)) * 256;  // k
                else              src = vw  + (head * 16 + (oc - 32)) * 256;        // v
                *reinterpret_cast<float4*>(&sm.wst[r][k4]) =
                    *reinterpret_cast<const float4*>(&src[kt + k4]);
            }
            __syncthreads();

            const float* wrow = &sm.wst[hh * 48 + oc16][0];
            #pragma unroll 4
            for (int kk = 0; kk < 32; kk += 4) {
                // 3 weight loads, half-warps share addresses: 2 wf each.
                const ulonglong2 w0 = *reinterpret_cast<const ulonglong2*>(&wrow[kk]);
                const ulonglong2 w1 = *reinterpret_cast<const ulonglong2*>(&wrow[16 * W_STRIDE + kk]);
                const ulonglong2 w2 = *reinterpret_cast<const ulonglong2*>(&wrow[32 * W_STRIDE + kk]);
                #pragma unroll
                for (int s = 0; s < 7; ++s) {
                    // 2 distinct addresses/warp, disjoint banks: 1 wf.
                    const ulonglong2 xv =
                        *reinterpret_cast<const ulonglong2*>(&sm.tok[t0 + s][kt + kk]);
                    FMA2(acc[0][s], w0.x, xv.x); FMA2(acc[0][s], w0.y, xv.y);
                    FMA2(acc[1][s], w1.x, xv.x); FMA2(acc[1][s], w1.y, xv.y);
                    FMA2(acc[2][s], w2.x, xv.x); FMA2(acc[2][s], w2.y, xv.y);
                }
            }
        }

        // Publish q|k|v transposed: row = hh*48 + oc16 + 16c (c=0:q, 1:k, 2:v->ReLU).
        #pragma unroll
        for (int c = 0; c < 3; ++c) {
            float* qrow = &sm.qt[hh * 48 + oc16 + 16 * c][0];
            #pragma unroll
            for (int s = 0; s < 7; ++s) {
                float v = hsum2(acc[c][s]);
                if (c == 2) v = fmaxf(v, 0.f);
                qrow[t0 + s] = v;
            }
        }
        __syncthreads();

        // ---------------- S = (q @ k^T) * 0.25, both heads in parallel ----------------
        {
            const int ah   = warp >> 2;
            const int wq2  = warp & 3;
            const int base = ah * 48;
            const bool act1 = (lane + 32) < 49;
            float q0[16], q1[16];
            #pragma unroll
            for (int d = 0; d < 16; ++d) {
                q0[d] = sm.qt[base + d][lane];                    // lane-consecutive
                q1[d] = act1 ? sm.qt[base + d][lane + 32] : 0.f;
            }
            #pragma unroll 1
            for (int jj = 0; jj < 13; ++jj) {
                const int j = wq2 * 13 + jj;
                if (j < 49) {
                    float s0 = 0.f, s1 = 0.f;
                    #pragma unroll
                    for (int d = 0; d < 16; ++d) {
                        const float kv = sm.qt[base + 16 + d][j];  // warp-uniform broadcast
                        s0 = fmaf(kv, q0[d], s0);
                        s1 = fmaf(kv, q1[d], s1);
                    }
                    sm.st[ah][j][lane] = s0 * 0.25f;
                    if (act1) sm.st[ah][j][lane + 32] = s1 * 0.25f;
                }
            }
        }
        __syncthreads();

        // ---------------- softmax over j (per query i, fully independent) ----------------
        if (tid < 98) {
            const int ah = tid >= 49;
            const int i  = tid - ah * 49;
            float m = -1e30f;
            #pragma unroll 7
            for (int j = 0; j < 49; ++j) m = fmaxf(m, sm.st[ah][j][i]);
            float sum = 0.f;
            #pragma unroll 7
            for (int j = 0; j < 49; ++j) {
                const float e = __expf(sm.st[ah][j][i] - m);
                sm.st[ah][j][i] = e;
                sum += e;
            }
            const float rs = 1.f / sum;
            #pragma unroll 7
            for (int j = 0; j < 49; ++j) sm.st[ah][j][i] *= rs;
        }
        __syncthreads();

        // ---------------- O = P @ V, scatter to (B, C, H, W) ----------------
        {
            const int ah   = warp >> 2;
            const int base = ah * 48 + 32;
            const int head = hp * 2 + ah;
            const bool act1 = (lane + 32) < 49;
            #pragma unroll
            for (int dd = 0; dd < 4; ++dd) {
                const int d = (warp & 3) * 4 + dd;
                float o0 = 0.f, o1 = 0.f;
                #pragma unroll 7
                for (int j = 0; j < 49; ++j) {
                    const float vb = sm.qt[base + d][j];          // warp-uniform broadcast
                    o0 = fmaf(vb, sm.st[ah][j][lane], o0);        // lane-consecutive
                    o1 = fmaf(vb, act1 ? sm.st[ah][j][lane + 32] : 0.f, o1);
                }
                const size_t ch = (size_t)(head * 16 + d) * 3136;
                {
                    const int i = lane, ti = i / 7, tj = i - (i / 7) * 7;
                    outb[ch + ti * 448 + tj * 8] = o0;
                }
                if (act1) {
                    const int i = lane + 32, ti = i / 7, tj = i - (i / 7) * 7;
                    outb[ch + ti * 448 + tj * 8] = o1;
                }
            }
        }
        __syncthreads();   // st / qt reuse ordering for next head pair
    }
}

extern "C" void kernel_launch(void* const* d_in, const int* in_sizes, int n_in,
                              void* d_out, int out_size) {
    const float* x   = (const float*)d_in[0];
    const float* g   = (const float*)d_in[1];
    const float* be  = (const float*)d_in[2];
    const float* mu  = (const float*)d_in[3];
    const float* var = (const float*)d_in[4];
    const float* qkw = (const float*)d_in[5];
    const float* vw  = (const float*)d_in[6];
    float* out = (float*)d_out;

    cudaFuncSetAttribute(wsa_kernel, cudaFuncAttributeMaxDynamicSharedMemorySize,
                         (int)sizeof(SmemT));
    wsa_kernel<<<4096, 256, sizeof(SmemT)>>>(x, g, be, mu, var, qkw, vw, out);
}